// round 14
// baseline (speedup 1.0000x reference)
#include <cuda_runtime.h>
#include <cuda_fp16.h>
#include <cstdint>
#include <cstddef>

// ---------------- problem constants ----------------
#define NN    2048
#define KNB   48
#define NF    384
#define MIN_  1536
#define NROWS (NN*KNB)        // 98304
#define LAYERS 3

// ---------------- device scratch ----------------
__device__ __half g_ET[(size_t)NROWS * NF];
__device__ __half g_H1[(size_t)NROWS * NF];
__device__ __half g_T [NN * MIN_];
__device__ __half g_Xt [NN * NF];
__device__ __half g_NT [NN * NF];
__device__ __half g_X1t[NN * NF];
__device__ __half g_Sb [NN * NF];
__device__ float  g_P  [(size_t)NN * 2 * NF];   // per-node partial sums from (d)
__device__ float  g_A  [NN * NF];
__device__ float  g_C  [NN * NF];
__device__ float  g_AGGP[3 * NN * NF];
__device__ float  g_DP  [3 * NN * NF];
__device__ float  g_X  [NN * NF];
__device__ float  g_X1 [NN * NF];
// transposed fp16 weights, [N][K] row-major (k-contiguous)
__device__ __half g_w0T [LAYERS * NF * MIN_];
__device__ __half g_w1T [LAYERS * NF * NF];
__device__ __half g_w2T [LAYERS * NF * NF];
__device__ __half g_dw0T[LAYERS * MIN_ * NF];
__device__ __half g_dw1T[LAYERS * NF * MIN_];

// ---------------- helpers ----------------
__device__ __forceinline__ float gelu_exact(float x) {
    return 0.5f * x * (1.0f + erff(x * 0.70710678118654752440f));
}

__device__ __forceinline__ void mma_f16(float* c, const uint32_t* a, const uint32_t* b) {
    asm volatile(
        "mma.sync.aligned.m16n8k16.row.col.f32.f16.f16.f32 "
        "{%0,%1,%2,%3}, {%4,%5,%6,%7}, {%8,%9}, {%0,%1,%2,%3};\n"
        : "+f"(c[0]), "+f"(c[1]), "+f"(c[2]), "+f"(c[3])
        : "r"(a[0]), "r"(a[1]), "r"(a[2]), "r"(a[3]),
          "r"(b[0]), "r"(b[1]));
}

#define LDSM_X4(r0, r1, r2, r3, addr) \
    asm volatile("ldmatrix.sync.aligned.m8n8.x4.shared.b16 {%0,%1,%2,%3}, [%4];" \
                 : "=r"(r0), "=r"(r1), "=r"(r2), "=r"(r3) : "r"(addr))

__device__ __forceinline__ void cp_async16(void* smem_dst, const void* gmem_src) {
    uint32_t s = (uint32_t)__cvta_generic_to_shared(smem_dst);
    asm volatile("cp.async.cg.shared.global [%0], [%1], 16;\n" :: "r"(s), "l"(gmem_src));
}
#define CP_COMMIT()  asm volatile("cp.async.commit_group;\n" ::: "memory")
#define CP_WAIT(n)   asm volatile("cp.async.wait_group %0;\n" :: "n"(n) : "memory")

// ============================================================
// FP16-input GEMM (fp32 acc), ldmatrix fragments, BK=64 / 3-stage cp.async,
// ONE __syncthreads per 64-wide K-iter, 2 CTAs/SM.  (R12 inner loop.)
// Template NWM = warps along M (4 -> BM=128, 2 -> BM=64). BN=128 fixed.
//   D[M,N] = epi( A[M,K] @ Bt[N,K]^T ), A stride lda, Bt stride ldB.
// flags: 1=gelu, 4=gather(addA[m/48]+addC[idx[m]]), 8=output fp16,
//        16=REDUCE: per-node column partial sums -> Pred (no D write)
// splitK>1: blockIdx.z = part p (fp32 parts at D + p*M*N, bias part0 only)
// splitK==1 && blockIdx.z==1: second problem (A2,Bt2,D2), no bias.
// ============================================================
#define BK 64
#define SROWB 144                     // bytes/row: 128B data + 16B pad (9 coprime 8)
#define STAGE_B (128*SROWB)           // 18432 B
#define NSTAGE 3
#define GEMM_SMEM_BYTES (2*NSTAGE*STAGE_B)   // 110592 B; x2 CTAs = 216KB
#define OSTR 132                      // reduce staging row stride (floats)

template<int NWM>
__global__ __launch_bounds__(256, 2) void gemm_f16_kernel(
    const __half* __restrict__ A, const __half* __restrict__ Bt,
    void* __restrict__ Dv, int M, int N, int K, int lda, int ldB,
    const float* __restrict__ bias, float alpha, float beta, int flags,
    const float* __restrict__ addA, const float* __restrict__ addC,
    const int* __restrict__ idxFlat,
    const __half* __restrict__ A2, const __half* __restrict__ Bt2,
    void* __restrict__ D2, float* __restrict__ Pred, int splitK)
{
    constexpr int BM_   = NWM * 32;
    constexpr int NWN   = 8 / NWM;
    constexpr int NCOLS = 128 / NWN;      // per-warp n columns
    constexpr int NI    = NCOLS / 8;      // 8 or 4

    if (splitK > 1) {
        const int part = blockIdx.z;
        const int Kp = K / splitK;
        A  += (size_t)part * Kp;
        Bt += (size_t)part * Kp;
        Dv = (void*)((float*)Dv + (size_t)part * M * N);
        if (part) bias = nullptr;
        K = Kp;
    } else if (blockIdx.z == 1) {
        A = A2; Bt = Bt2; Dv = D2; bias = nullptr;
    }

    extern __shared__ char smc[];   // [A x NSTAGE][B x NSTAGE]
    const uint32_t sbase = (uint32_t)__cvta_generic_to_shared(smc);

    const int tid  = threadIdx.x;
    const int m0   = blockIdx.x * BM_;
    const int n0   = blockIdx.y * 128;
    const int warp = tid >> 5;
    const int lane = tid & 31;
    const int wm   = warp / NWN;
    const int wn   = warp % NWN;
    const int gid  = lane >> 2;
    const int tig  = lane & 3;

    float acc[2][NI][4];
    #pragma unroll
    for (int a = 0; a < 2; a++)
        #pragma unroll
        for (int b = 0; b < NI; b++)
            #pragma unroll
            for (int c = 0; c < 4; c++) acc[a][b][c] = 0.f;

    // ldmatrix fragment base addresses (bytes, stage 0)
    const uint32_t aFrag = sbase +
        (uint32_t)((wm * 32 + (lane & 15)) * SROWB + (lane >> 4) * 16);
    const uint32_t bFrag = sbase + (uint32_t)(NSTAGE * STAGE_B) +
        (uint32_t)(((wn * NCOLS + ((lane >> 4) * 8) + (lane & 7)) * SROWB) +
                   (((lane >> 3) & 1) * 16));

    // loop-invariant produce coordinates
    const int prow = tid >> 3;            // 0..31
    const int pch  = (tid & 7) * 16;      // smem byte offset within row
    const __half* aSrc0 = A  + (size_t)(m0 + prow) * lda + (tid & 7) * 8;
    const __half* bSrc0 = Bt + (size_t)(n0 + prow) * ldB + (tid & 7) * 8;
    const int KT = K / BK;

    auto produce = [&](int kt, int buf) {
        const __half* Ap = aSrc0 + kt * BK;
        char* As = smc + buf * STAGE_B + prow * SROWB + pch;
        #pragma unroll
        for (int i = 0; i < BM_ / 32; i++)
            cp_async16(As + i * 32 * SROWB, Ap + (size_t)i * 32 * lda);
        const __half* Bp = bSrc0 + kt * BK;
        char* Bs = smc + (NSTAGE + buf) * STAGE_B + prow * SROWB + pch;
        #pragma unroll
        for (int i = 0; i < 4; i++)
            cp_async16(Bs + i * 32 * SROWB, Bp + (size_t)i * 32 * ldB);
        CP_COMMIT();
    };

    // prologue: 2 stages ahead
    produce(0, 0);
    if (KT > 1) produce(1, 1);

    for (int kt = 0; kt < KT; kt++) {
        const int cur = kt % NSTAGE;
        if (kt + 1 < KT) { CP_WAIT(1); }
        else             { CP_WAIT(0); }
        __syncthreads();

        const uint32_t so = (uint32_t)(cur * STAGE_B);
        #pragma unroll
        for (int j = 0; j < 4; j++) {         // four k16 steps per BK=64
            const uint32_t aA = aFrag + so + j * 32;
            const uint32_t bA = bFrag + so + j * 32;
            uint32_t a0[4], a1[4], bf[NI][2];
            LDSM_X4(a0[0], a0[1], a0[2], a0[3], aA);
            LDSM_X4(a1[0], a1[1], a1[2], a1[3], aA + 16 * SROWB);
            #pragma unroll
            for (int gg = 0; gg < NI / 2; gg++)
                LDSM_X4(bf[2*gg][0], bf[2*gg][1], bf[2*gg+1][0], bf[2*gg+1][1],
                        bA + (uint32_t)(gg * 16 * SROWB));
            #pragma unroll
            for (int ni = 0; ni < NI; ni++) {
                mma_f16(acc[0][ni], a0, bf[ni]);
                mma_f16(acc[1][ni], a1, bf[ni]);
            }
        }
        if (kt + 2 < KT) produce(kt + 2, (kt + 2) % NSTAGE);
    }

    // ---- epilogue ----
    const int doGelu  = flags & 1;
    const int doGath  = flags & 4;
    const int outHalf = flags & 8;
    const int doRed   = flags & 16;
    float* Os = (float*)smc;                    // [BM_][OSTR], reuse pipeline smem
    if (doRed) __syncthreads();                 // all LDSM readers done

    #pragma unroll
    for (int mi = 0; mi < 2; mi++) {
        #pragma unroll
        for (int h = 0; h < 2; h++) {
            const int r = wm * 32 + mi * 16 + h * 8 + gid;
            const int m = m0 + r;
            const float* aArow = nullptr;
            const float* aCrow = nullptr;
            if (doGath) {
                aArow = addA + (size_t)(m / KNB) * N;
                aCrow = addC + (size_t)idxFlat[m] * N;
            }
            #pragma unroll
            for (int ni = 0; ni < NI; ni++) {
                const int n = n0 + wn * NCOLS + ni * 8 + tig * 2;
                float v0 = acc[mi][ni][h * 2 + 0] * alpha;
                float v1 = acc[mi][ni][h * 2 + 1] * alpha;
                if (bias) { v0 += beta * bias[n]; v1 += beta * bias[n + 1]; }
                if (doGath) {
                    v0 += aArow[n] + aCrow[n];
                    v1 += aArow[n + 1] + aCrow[n + 1];
                }
                if (doGelu) { v0 = gelu_exact(v0); v1 = gelu_exact(v1); }
                if (doRed) {
                    Os[r * OSTR + (n - n0)]     = v0;
                    Os[r * OSTR + (n - n0) + 1] = v1;
                } else if (outHalf) {
                    __half2* Drow = (__half2*)((__half*)Dv + (size_t)m * N + n);
                    *Drow = __floats2half2_rn(v0, v1);
                } else {
                    float2* Drow = (float2*)((float*)Dv + (size_t)m * N + n);
                    *Drow = make_float2(v0, v1);
                }
            }
        }
    }

    if (doRed) {
        __syncthreads();
        // deterministic per-node partial sums: a node's 48 rows span <= 2 tiles
        const int nfirst = m0 / KNB;
        const int nlast  = (m0 + BM_ - 1) / KNB;
        for (int node = nfirst; node <= nlast; node++) {
            int lo = KNB * node - m0;        if (lo < 0) lo = 0;
            int hi = KNB * node + KNB - m0;  if (hi > BM_) hi = BM_;
            const int  slot = (KNB * node >= m0) ? 0 : 1;
            const bool full = (KNB * node >= m0) && (KNB * node + KNB <= m0 + BM_);
            for (int c = tid; c < 128; c += 256) {
                float s = 0.f;
                for (int r = lo; r < hi; r++) s += Os[r * OSTR + c];
                Pred[((size_t)node * 2 + slot) * N + n0 + c] = s;
                if (full) Pred[((size_t)node * 2 + 1) * N + n0 + c] = 0.f;
            }
        }
    }
}

// ---------------- supporting kernels ----------------
// S = fp16(P0 + P1)
__global__ void combine_kernel(const float* __restrict__ P, __half* __restrict__ S) {
    int i = blockIdx.x;
    int n = threadIdx.x;
    float v = P[((size_t)i * 2) * NF + n] + P[((size_t)i * 2 + 1) * NF + n];
    S[(size_t)i * NF + n] = __float2half(v);
}

// layernorm of (a + p0 [+ p1] [+ p2]); out (fp32), out2 (fp16, optional); mask optional
__global__ void ln_kernel(const float* __restrict__ a,
                          const float* __restrict__ p0,
                          const float* __restrict__ p1,
                          const float* __restrict__ p2,
                          const float* __restrict__ w, const float* __restrict__ bv,
                          const float* __restrict__ mask,
                          float* __restrict__ out, __half* __restrict__ out2)
{
    int i = blockIdx.x;
    int n = threadIdx.x;
    size_t o = (size_t)i * NF + n;
    float v = a[o] + p0[o];
    if (p1) v += p1[o];
    if (p2) v += p2[o];

    __shared__ float s1[12], s2[12];
    float x1 = v, x2 = v * v;
    #pragma unroll
    for (int off = 16; off; off >>= 1) {
        x1 += __shfl_down_sync(0xFFFFFFFFu, x1, off);
        x2 += __shfl_down_sync(0xFFFFFFFFu, x2, off);
    }
    int wi = n >> 5, li = n & 31;
    if (li == 0) { s1[wi] = x1; s2[wi] = x2; }
    __syncthreads();
    __shared__ float mean_s, rstd_s;
    if (n == 0) {
        float t1 = 0.f, t2 = 0.f;
        #pragma unroll
        for (int j = 0; j < 12; j++) { t1 += s1[j]; t2 += s2[j]; }
        float mu  = t1 * (1.f / NF);
        float var = t2 * (1.f / NF) - mu * mu;
        mean_s = mu;
        rstd_s = rsqrtf(var + 1e-5f);
    }
    __syncthreads();
    float rr = (v - mean_s) * rstd_s * w[n] + bv[n];
    if (mask) rr *= mask[i];
    out[o] = rr;
    if (out2) out2[o] = __float2half(rr);
}

// merged preamble: edges fp32->fp16 AND node -> X(fp32), Xt(fp16), NT(fp16)
#define N4E ((size_t)NROWS * NF / 4)
#define N4N (NN * NF / 4)
__global__ void prep_kernel(const float* __restrict__ edges, __half* __restrict__ ET,
                            const float* __restrict__ node, float* __restrict__ X,
                            __half* __restrict__ Xt, __half* __restrict__ NT)
{
    size_t i = (size_t)blockIdx.x * blockDim.x + threadIdx.x;
    if (i < N4E) {
        float4 v = reinterpret_cast<const float4*>(edges)[i];
        __half2* d = reinterpret_cast<__half2*>(ET + i * 4);
        d[0] = __floats2half2_rn(v.x, v.y);
        d[1] = __floats2half2_rn(v.z, v.w);
    }
    if (i < N4N) {
        float4 v = reinterpret_cast<const float4*>(node)[i];
        reinterpret_cast<float4*>(X)[i] = v;
        __half2 h0 = __floats2half2_rn(v.x, v.y);
        __half2 h1 = __floats2half2_rn(v.z, v.w);
        __half2* xt = reinterpret_cast<__half2*>(Xt + i * 4);
        __half2* nt = reinterpret_cast<__half2*>(NT + i * 4);
        xt[0] = h0; xt[1] = h1;
        nt[0] = h0; nt[1] = h1;
    }
}

// all weight transposes (fp32 [K,N] -> fp16 [N,K]) in one launch; z = type*3 + layer
__global__ void transpose_all_kernel(
    const float* __restrict__ w0,  const float* __restrict__ w1,
    const float* __restrict__ w2,  const float* __restrict__ dw0,
    const float* __restrict__ dw1,
    __half* __restrict__ w0T,  __half* __restrict__ w1T,
    __half* __restrict__ w2T,  __half* __restrict__ dw0T,
    __half* __restrict__ dw1T)
{
    const int z = blockIdx.z;
    const int type = z / 3, layer = z % 3;
    const float* in; __half* out; int K, N;
    switch (type) {
        case 0: in = w0  + (size_t)layer*MIN_*NF; out = w0T  + (size_t)layer*NF*MIN_; K = MIN_; N = NF;   break;
        case 1: in = w1  + (size_t)layer*NF*NF;   out = w1T  + (size_t)layer*NF*NF;   K = NF;   N = NF;   break;
        case 2: in = w2  + (size_t)layer*NF*NF;   out = w2T  + (size_t)layer*NF*NF;   K = NF;   N = NF;   break;
        case 3: in = dw0 + (size_t)layer*NF*MIN_; out = dw0T + (size_t)layer*MIN_*NF; K = NF;   N = MIN_; break;
        default:in = dw1 + (size_t)layer*MIN_*NF; out = dw1T + (size_t)layer*NF*MIN_; K = MIN_; N = NF;   break;
    }
    const int k0 = blockIdx.x * 32, n0 = blockIdx.y * 32;
    if (k0 >= K || n0 >= N) return;

    __shared__ float t[32][33];
    const int x = threadIdx.x, y = threadIdx.y;
    #pragma unroll
    for (int i = y; i < 32; i += 8)
        t[i][x] = in[(size_t)(k0 + i) * N + n0 + x];
    __syncthreads();
    #pragma unroll
    for (int i = y; i < 32; i += 8)
        out[(size_t)(n0 + i) * K + k0 + x] = __float2half(t[x][i]);
}

// ---------------- host orchestration ----------------
static inline void launch_gemm(bool smallTile,
                               const __half* A, const __half* Bt, void* D,
                               int M, int N, int K, int lda, int ldB,
                               const float* bias, float alpha, float beta, int flags,
                               const float* addA = nullptr, const float* addC = nullptr,
                               const int* idxFlat = nullptr,
                               const __half* A2 = nullptr, const __half* Bt2 = nullptr,
                               void* D2 = nullptr, float* Pred = nullptr, int splitK = 1)
{
    const int bm = smallTile ? 64 : 128;
    dim3 grid(M / bm, N / 128, splitK > 1 ? splitK : (A2 ? 2 : 1));
    if (smallTile)
        gemm_f16_kernel<2><<<grid, 256, GEMM_SMEM_BYTES>>>(A, Bt, D, M, N, K, lda, ldB,
                                                           bias, alpha, beta, flags,
                                                           addA, addC, idxFlat,
                                                           A2, Bt2, D2, Pred, splitK);
    else
        gemm_f16_kernel<4><<<grid, 256, GEMM_SMEM_BYTES>>>(A, Bt, D, M, N, K, lda, ldB,
                                                           bias, alpha, beta, flags,
                                                           addA, addC, idxFlat,
                                                           A2, Bt2, D2, Pred, splitK);
}

extern "C" void kernel_launch(void* const* d_in, const int* in_sizes, int n_in,
                              void* d_out, int out_size)
{
    (void)in_sizes; (void)n_in; (void)out_size;

    const float* node  = (const float*)d_in[0];
    const float* edges = (const float*)d_in[1];
    const int*   nidx  = (const int*)  d_in[2];
    const float* mask  = (const float*)d_in[3];
    const float* w0    = (const float*)d_in[4];
    const float* b0    = (const float*)d_in[5];
    const float* w1    = (const float*)d_in[6];
    const float* b1    = (const float*)d_in[7];
    const float* w2    = (const float*)d_in[8];
    const float* b2    = (const float*)d_in[9];
    const float* ln1w  = (const float*)d_in[10];
    const float* ln1b  = (const float*)d_in[11];
    const float* dw0   = (const float*)d_in[12];
    const float* db0   = (const float*)d_in[13];
    const float* dw1   = (const float*)d_in[14];
    const float* db1   = (const float*)d_in[15];
    const float* ln2w  = (const float*)d_in[16];
    const float* ln2b  = (const float*)d_in[17];

    __half *ET, *H1, *T, *Xt, *NT, *X1t, *Sb;
    __half *w0T, *w1T, *w2T, *dw0T, *dw1T;
    float *Pp, *Ab, *Cb, *AGGP, *DP, *X, *X1;
    cudaGetSymbolAddress((void**)&ET,   g_ET);
    cudaGetSymbolAddress((void**)&H1,   g_H1);
    cudaGetSymbolAddress((void**)&T,    g_T);
    cudaGetSymbolAddress((void**)&Xt,   g_Xt);
    cudaGetSymbolAddress((void**)&NT,   g_NT);
    cudaGetSymbolAddress((void**)&X1t,  g_X1t);
    cudaGetSymbolAddress((void**)&Sb,   g_Sb);
    cudaGetSymbolAddress((void**)&Pp,   g_P);
    cudaGetSymbolAddress((void**)&Ab,   g_A);
    cudaGetSymbolAddress((void**)&Cb,   g_C);
    cudaGetSymbolAddress((void**)&AGGP, g_AGGP);
    cudaGetSymbolAddress((void**)&DP,   g_DP);
    cudaGetSymbolAddress((void**)&X,    g_X);
    cudaGetSymbolAddress((void**)&X1,   g_X1);
    cudaGetSymbolAddress((void**)&w0T,  g_w0T);
    cudaGetSymbolAddress((void**)&w1T,  g_w1T);
    cudaGetSymbolAddress((void**)&w2T,  g_w2T);
    cudaGetSymbolAddress((void**)&dw0T, g_dw0T);
    cudaGetSymbolAddress((void**)&dw1T, g_dw1T);

    cudaFuncSetAttribute(gemm_f16_kernel<4>,
                         cudaFuncAttributeMaxDynamicSharedMemorySize, GEMM_SMEM_BYTES);
    cudaFuncSetAttribute(gemm_f16_kernel<2>,
                         cudaFuncAttributeMaxDynamicSharedMemorySize, GEMM_SMEM_BYTES);

    // ---- preamble: 2 launches, so launch #3 is the big (c) GEMM for ncu ----
    prep_kernel<<<(int)((N4E + 255) / 256), 256>>>(edges, ET, node, X, Xt, NT);  // 0
    transpose_all_kernel<<<dim3(48, 48, 15), dim3(32, 8)>>>(
        w0, w1, w2, dw0, dw1, w0T, w1T, w2T, dw0T, dw1T);                        // 1

    for (int i = 0; i < LAYERS; i++) {
        const __half* w0L  = w0T  + (size_t)i * NF * MIN_;
        const float*  b0L  = b0   + (size_t)i * NF;
        const __half* w1L  = w1T  + (size_t)i * NF * NF;
        const float*  b1L  = b1   + (size_t)i * NF;
        const __half* w2L  = w2T  + (size_t)i * NF * NF;
        const float*  b2L  = b2   + (size_t)i * NF;
        const __half* dw0L = dw0T + (size_t)i * MIN_ * NF;
        const float*  db0L = db0  + (size_t)i * MIN_;
        const __half* dw1L = dw1T + (size_t)i * NF * MIN_;
        const float*  db1L = db1  + (size_t)i * NF;

        // (a)+(b) merged (small tile): Ab = x@W0a + b0 ; Cb = node@W0d   (launch 2)
        launch_gemm(true, Xt, w0L, Ab, NN, NF, NF, NF, MIN_, b0L, 1.f, 1.f, 0,
                    nullptr, nullptr, nullptr,
                    NT, w0L + 1152, Cb);
        // (c) H1 = fp16(gelu(edges @ W0b + A[m/48] + C[idx]))            (launch 3 <- ncu)
        launch_gemm(false, ET, w0L + 384, H1, NROWS, NF, NF, NF, MIN_,
                    nullptr, 1.f, 0.f, 1 | 4 | 8, Ab, Cb, nidx);
        // (d)+(e) fused: gelu(H1 @ W1 + b1) -> per-node partial sums P (no H2)
        launch_gemm(false, H1, w1L, nullptr, NROWS, NF, NF, NF, NF, b1L, 1.f, 1.f,
                    1 | 16, nullptr, nullptr, nullptr, nullptr, nullptr, nullptr, Pp);
        // (e') S = fp16(P0 + P1)
        combine_kernel<<<NN, NF>>>(Pp, Sb);
        // (f) AGG parts = (S @ W2)/30 (+ (48/30) b2 in part 0), split-K=3 (small tile)
        launch_gemm(true, Sb, w2L, AGGP, NN, NF, NF, NF, NF, b2L,
                    1.f / 30.f, 48.f / 30.f, 0,
                    nullptr, nullptr, nullptr, nullptr, nullptr, nullptr, nullptr, 3);
        // (g) x1 = LN(x + sum AGG parts)
        ln_kernel<<<NN, NF>>>(X, AGGP, AGGP + (size_t)NN * NF, AGGP + (size_t)2 * NN * NF,
                              ln1w + (size_t)i * NF, ln1b + (size_t)i * NF,
                              nullptr, X1, X1t);
        // (h) T = fp16(gelu(x1 @ dense_w0 + db0))
        launch_gemm(false, X1t, dw0L, T, NN, MIN_, NF, NF, NF, db0L, 1.f, 1.f, 1 | 8);
        // (i) D parts = T @ dense_w1 (+ db1 in part 0), split-K=3 (small tile)
        launch_gemm(true, T, dw1L, DP, NN, NF, MIN_, MIN_, MIN_, db1L, 1.f, 1.f, 0,
                    nullptr, nullptr, nullptr, nullptr, nullptr, nullptr, nullptr, 3);
        // (j) x = mask * LN(x1 + sum D parts)
        float*  xout  = (i == LAYERS - 1) ? (float*)d_out : X;
        __half* xout2 = (i == LAYERS - 1) ? nullptr : Xt;
        ln_kernel<<<NN, NF>>>(X1, DP, DP + (size_t)NN * NF, DP + (size_t)2 * NN * NF,
                              ln2w + (size_t)i * NF, ln2b + (size_t)i * NF,
                              mask, xout, xout2);
    }
}

// round 15
// speedup vs baseline: 1.1963x; 1.1963x over previous
#include <cuda_runtime.h>
#include <cuda_fp16.h>
#include <cstdint>
#include <cstddef>

// ---------------- problem constants ----------------
#define NN    2048
#define KNB   48
#define NF    384
#define MIN_  1536
#define NROWS (NN*KNB)        // 98304
#define LAYERS 3

// ---------------- device scratch ----------------
__device__ __half g_ET[(size_t)NROWS * NF];
__device__ __half g_H1[(size_t)NROWS * NF];
__device__ __half g_T [NN * MIN_];
__device__ __half g_Xt [NN * NF];
__device__ __half g_NT [NN * NF];
__device__ __half g_X1t[NN * NF];
__device__ __half g_Sb [NN * NF];
__device__ float  g_P  [(size_t)NN * 2 * NF];
__device__ float  g_A  [NN * NF];
__device__ float  g_C  [NN * NF];
__device__ float  g_AGGP[3 * NN * NF];
__device__ float  g_DP  [3 * NN * NF];
__device__ float  g_X  [NN * NF];
__device__ float  g_X1 [NN * NF];
// transposed fp16 weights, [N][K] row-major (k-contiguous)
__device__ __half g_w0T [LAYERS * NF * MIN_];
__device__ __half g_w1T [LAYERS * NF * NF];
__device__ __half g_w2T [LAYERS * NF * NF];
__device__ __half g_dw0T[LAYERS * MIN_ * NF];
__device__ __half g_dw1T[LAYERS * NF * MIN_];

// ---------------- helpers ----------------
__device__ __forceinline__ float gelu_exact(float x) {
    return 0.5f * x * (1.0f + erff(x * 0.70710678118654752440f));
}

__device__ __forceinline__ void mma_f16(float* c, const uint32_t* a, const uint32_t* b) {
    asm volatile(
        "mma.sync.aligned.m16n8k16.row.col.f32.f16.f16.f32 "
        "{%0,%1,%2,%3}, {%4,%5,%6,%7}, {%8,%9}, {%0,%1,%2,%3};\n"
        : "+f"(c[0]), "+f"(c[1]), "+f"(c[2]), "+f"(c[3])
        : "r"(a[0]), "r"(a[1]), "r"(a[2]), "r"(a[3]),
          "r"(b[0]), "r"(b[1]));
}

#define LDSM_X4(r0, r1, r2, r3, addr) \
    asm volatile("ldmatrix.sync.aligned.m8n8.x4.shared.b16 {%0,%1,%2,%3}, [%4];" \
                 : "=r"(r0), "=r"(r1), "=r"(r2), "=r"(r3) : "r"(addr))

__device__ __forceinline__ void cp_async16(void* smem_dst, const void* gmem_src) {
    uint32_t s = (uint32_t)__cvta_generic_to_shared(smem_dst);
    asm volatile("cp.async.cg.shared.global [%0], [%1], 16;\n" :: "r"(s), "l"(gmem_src));
}
#define CP_COMMIT()  asm volatile("cp.async.commit_group;\n" ::: "memory")
#define CP_WAIT(n)   asm volatile("cp.async.wait_group %0;\n" :: "n"(n) : "memory")

// ============================================================
// FP16-input GEMM (fp32 acc), ldmatrix fragments, BK=64 / 3-stage cp.async,
// ONE __syncthreads per 64-wide K-iter, 2 CTAs/SM.  (R12 inner loop.)
// Template NWM = warps along M (4 -> BM=128, 2 -> BM=64). BN=128 fixed.
// Template DORED: compile-time fused per-node reduction (only the (d) launch).
//   D[M,N] = epi( A[M,K] @ Bt[N,K]^T ), A stride lda, Bt stride ldB.
// flags: 1=gelu, 4=gather(addA[m/48]+addC[idx[m]]), 8=output fp16
// splitK>1: blockIdx.z = part p (fp32 parts at D + p*M*N, bias part0 only)
// splitK==1 && blockIdx.z==1: second problem (A2,Bt2,D2), no bias.
// ============================================================
#define BK 64
#define SROWB 144                     // bytes/row: 128B data + 16B pad (9 coprime 8)
#define STAGE_B (128*SROWB)           // 18432 B
#define NSTAGE 3
#define GEMM_SMEM_BYTES (2*NSTAGE*STAGE_B)   // 110592 B; x2 CTAs = 216KB
#define OSTR 132                      // reduce staging row stride (floats)

template<int NWM, bool DORED>
__global__ __launch_bounds__(256, 2) void gemm_f16_kernel(
    const __half* __restrict__ A, const __half* __restrict__ Bt,
    void* __restrict__ Dv, int M, int N, int K, int lda, int ldB,
    const float* __restrict__ bias, float alpha, float beta, int flags,
    const float* __restrict__ addA, const float* __restrict__ addC,
    const int* __restrict__ idxFlat,
    const __half* __restrict__ A2, const __half* __restrict__ Bt2,
    void* __restrict__ D2, float* __restrict__ Pred, int splitK)
{
    constexpr int BM_   = NWM * 32;
    constexpr int NWN   = 8 / NWM;
    constexpr int NCOLS = 128 / NWN;      // per-warp n columns
    constexpr int NI    = NCOLS / 8;      // 8 or 4

    if (splitK > 1) {
        const int part = blockIdx.z;
        const int Kp = K / splitK;
        A  += (size_t)part * Kp;
        Bt += (size_t)part * Kp;
        Dv = (void*)((float*)Dv + (size_t)part * M * N);
        if (part) bias = nullptr;
        K = Kp;
    } else if (blockIdx.z == 1) {
        A = A2; Bt = Bt2; Dv = D2; bias = nullptr;
    }

    extern __shared__ char smc[];   // [A x NSTAGE][B x NSTAGE]
    const uint32_t sbase = (uint32_t)__cvta_generic_to_shared(smc);

    const int tid  = threadIdx.x;
    const int m0   = blockIdx.x * BM_;
    const int n0   = blockIdx.y * 128;
    const int warp = tid >> 5;
    const int lane = tid & 31;
    const int wm   = warp / NWN;
    const int wn   = warp % NWN;
    const int gid  = lane >> 2;
    const int tig  = lane & 3;

    float acc[2][NI][4];
    #pragma unroll
    for (int a = 0; a < 2; a++)
        #pragma unroll
        for (int b = 0; b < NI; b++)
            #pragma unroll
            for (int c = 0; c < 4; c++) acc[a][b][c] = 0.f;

    // ldmatrix fragment base addresses (bytes, stage 0)
    const uint32_t aFrag = sbase +
        (uint32_t)((wm * 32 + (lane & 15)) * SROWB + (lane >> 4) * 16);
    const uint32_t bFrag = sbase + (uint32_t)(NSTAGE * STAGE_B) +
        (uint32_t)(((wn * NCOLS + ((lane >> 4) * 8) + (lane & 7)) * SROWB) +
                   (((lane >> 3) & 1) * 16));

    // loop-invariant produce coordinates
    const int prow = tid >> 3;            // 0..31
    const int pch  = (tid & 7) * 16;      // smem byte offset within row
    const __half* aSrc0 = A  + (size_t)(m0 + prow) * lda + (tid & 7) * 8;
    const __half* bSrc0 = Bt + (size_t)(n0 + prow) * ldB + (tid & 7) * 8;
    const int KT = K / BK;

    auto produce = [&](int kt, int buf) {
        const __half* Ap = aSrc0 + kt * BK;
        char* As = smc + buf * STAGE_B + prow * SROWB + pch;
        #pragma unroll
        for (int i = 0; i < BM_ / 32; i++)
            cp_async16(As + i * 32 * SROWB, Ap + (size_t)i * 32 * lda);
        const __half* Bp = bSrc0 + kt * BK;
        char* Bs = smc + (NSTAGE + buf) * STAGE_B + prow * SROWB + pch;
        #pragma unroll
        for (int i = 0; i < 4; i++)
            cp_async16(Bs + i * 32 * SROWB, Bp + (size_t)i * 32 * ldB);
        CP_COMMIT();
    };

    // prologue: 2 stages ahead
    produce(0, 0);
    if (KT > 1) produce(1, 1);

    for (int kt = 0; kt < KT; kt++) {
        const int cur = kt % NSTAGE;
        if (kt + 1 < KT) { CP_WAIT(1); }
        else             { CP_WAIT(0); }
        __syncthreads();

        const uint32_t so = (uint32_t)(cur * STAGE_B);
        #pragma unroll
        for (int j = 0; j < 4; j++) {         // four k16 steps per BK=64
            const uint32_t aA = aFrag + so + j * 32;
            const uint32_t bA = bFrag + so + j * 32;
            uint32_t a0[4], a1[4], bf[NI][2];
            LDSM_X4(a0[0], a0[1], a0[2], a0[3], aA);
            LDSM_X4(a1[0], a1[1], a1[2], a1[3], aA + 16 * SROWB);
            #pragma unroll
            for (int gg = 0; gg < NI / 2; gg++)
                LDSM_X4(bf[2*gg][0], bf[2*gg][1], bf[2*gg+1][0], bf[2*gg+1][1],
                        bA + (uint32_t)(gg * 16 * SROWB));
            #pragma unroll
            for (int ni = 0; ni < NI; ni++) {
                mma_f16(acc[0][ni], a0, bf[ni]);
                mma_f16(acc[1][ni], a1, bf[ni]);
            }
        }
        if (kt + 2 < KT) produce(kt + 2, (kt + 2) % NSTAGE);
    }

    // ---- epilogue ----
    const int doGelu  = flags & 1;
    const int doGath  = flags & 4;
    const int outHalf = flags & 8;

    if constexpr (DORED) {
        float* Os = (float*)smc;               // reuse pipeline smem post-loop
        __syncthreads();
        #pragma unroll
        for (int mi = 0; mi < 2; mi++) {
            #pragma unroll
            for (int h = 0; h < 2; h++) {
                const int r = wm * 32 + mi * 16 + h * 8 + gid;
                #pragma unroll
                for (int ni = 0; ni < NI; ni++) {
                    const int nl = wn * NCOLS + ni * 8 + tig * 2;
                    float v0 = acc[mi][ni][h * 2 + 0];
                    float v1 = acc[mi][ni][h * 2 + 1];
                    if (bias) { v0 += bias[n0 + nl]; v1 += bias[n0 + nl + 1]; }
                    v0 = gelu_exact(v0);
                    v1 = gelu_exact(v1);
                    Os[r * OSTR + nl]     = v0;
                    Os[r * OSTR + nl + 1] = v1;
                }
            }
        }
        __syncthreads();
        // deterministic per-node partial sums: a node's 48 rows span <= 2 tiles
        const int nfirst = m0 / KNB;
        const int nlast  = (m0 + BM_ - 1) / KNB;
        for (int node = nfirst; node <= nlast; node++) {
            int lo = KNB * node - m0;        if (lo < 0) lo = 0;
            int hi = KNB * node + KNB - m0;  if (hi > BM_) hi = BM_;
            const int  slot = (KNB * node >= m0) ? 0 : 1;
            const bool full = (KNB * node >= m0) && (KNB * node + KNB <= m0 + BM_);
            for (int c = tid; c < 128; c += 256) {
                float s = 0.f;
                for (int r = lo; r < hi; r++) s += Os[r * OSTR + c];
                Pred[((size_t)node * 2 + slot) * N + n0 + c] = s;
                if (full) Pred[((size_t)node * 2 + 1) * N + n0 + c] = 0.f;
            }
        }
        return;
    }

    #pragma unroll
    for (int mi = 0; mi < 2; mi++) {
        #pragma unroll
        for (int h = 0; h < 2; h++) {
            const int m = m0 + wm * 32 + mi * 16 + h * 8 + gid;
            const float* aArow = nullptr;
            const float* aCrow = nullptr;
            if (doGath) {
                aArow = addA + (size_t)(m / KNB) * N;
                aCrow = addC + (size_t)idxFlat[m] * N;
            }
            #pragma unroll
            for (int ni = 0; ni < NI; ni++) {
                const int n = n0 + wn * NCOLS + ni * 8 + tig * 2;
                float v0 = acc[mi][ni][h * 2 + 0] * alpha;
                float v1 = acc[mi][ni][h * 2 + 1] * alpha;
                if (bias) { v0 += beta * bias[n]; v1 += beta * bias[n + 1]; }
                if (doGath) {
                    v0 += aArow[n] + aCrow[n];
                    v1 += aArow[n + 1] + aCrow[n + 1];
                }
                if (doGelu) { v0 = gelu_exact(v0); v1 = gelu_exact(v1); }
                if (outHalf) {
                    __half2* Drow = (__half2*)((__half*)Dv + (size_t)m * N + n);
                    *Drow = __floats2half2_rn(v0, v1);
                } else {
                    float2* Drow = (float2*)((float*)Dv + (size_t)m * N + n);
                    *Drow = make_float2(v0, v1);
                }
            }
        }
    }
}

// ---------------- supporting kernels ----------------
// S = fp16(P0 + P1)
__global__ void combine_kernel(const float* __restrict__ P, __half* __restrict__ S) {
    int i = blockIdx.x;
    int n = threadIdx.x;
    float v = P[((size_t)i * 2) * NF + n] + P[((size_t)i * 2 + 1) * NF + n];
    S[(size_t)i * NF + n] = __float2half(v);
}

// layernorm of (a + p0 [+ p1] [+ p2]); out (fp32), out2 (fp16, optional); mask optional
__global__ void ln_kernel(const float* __restrict__ a,
                          const float* __restrict__ p0,
                          const float* __restrict__ p1,
                          const float* __restrict__ p2,
                          const float* __restrict__ w, const float* __restrict__ bv,
                          const float* __restrict__ mask,
                          float* __restrict__ out, __half* __restrict__ out2)
{
    int i = blockIdx.x;
    int n = threadIdx.x;
    size_t o = (size_t)i * NF + n;
    float v = a[o] + p0[o];
    if (p1) v += p1[o];
    if (p2) v += p2[o];

    __shared__ float s1[12], s2[12];
    float x1 = v, x2 = v * v;
    #pragma unroll
    for (int off = 16; off; off >>= 1) {
        x1 += __shfl_down_sync(0xFFFFFFFFu, x1, off);
        x2 += __shfl_down_sync(0xFFFFFFFFu, x2, off);
    }
    int wi = n >> 5, li = n & 31;
    if (li == 0) { s1[wi] = x1; s2[wi] = x2; }
    __syncthreads();
    __shared__ float mean_s, rstd_s;
    if (n == 0) {
        float t1 = 0.f, t2 = 0.f;
        #pragma unroll
        for (int j = 0; j < 12; j++) { t1 += s1[j]; t2 += s2[j]; }
        float mu  = t1 * (1.f / NF);
        float var = t2 * (1.f / NF) - mu * mu;
        mean_s = mu;
        rstd_s = rsqrtf(var + 1e-5f);
    }
    __syncthreads();
    float rr = (v - mean_s) * rstd_s * w[n] + bv[n];
    if (mask) rr *= mask[i];
    out[o] = rr;
    if (out2) out2[o] = __float2half(rr);
}

// merged preamble: edges fp32->fp16 AND node -> X(fp32), Xt(fp16), NT(fp16)
#define N4E ((size_t)NROWS * NF / 4)
#define N4N (NN * NF / 4)
__global__ void prep_kernel(const float* __restrict__ edges, __half* __restrict__ ET,
                            const float* __restrict__ node, float* __restrict__ X,
                            __half* __restrict__ Xt, __half* __restrict__ NT)
{
    size_t i = (size_t)blockIdx.x * blockDim.x + threadIdx.x;
    if (i < N4E) {
        float4 v = reinterpret_cast<const float4*>(edges)[i];
        __half2* d = reinterpret_cast<__half2*>(ET + i * 4);
        d[0] = __floats2half2_rn(v.x, v.y);
        d[1] = __floats2half2_rn(v.z, v.w);
    }
    if (i < N4N) {
        float4 v = reinterpret_cast<const float4*>(node)[i];
        reinterpret_cast<float4*>(X)[i] = v;
        __half2 h0 = __floats2half2_rn(v.x, v.y);
        __half2 h1 = __floats2half2_rn(v.z, v.w);
        __half2* xt = reinterpret_cast<__half2*>(Xt + i * 4);
        __half2* nt = reinterpret_cast<__half2*>(NT + i * 4);
        xt[0] = h0; xt[1] = h1;
        nt[0] = h0; nt[1] = h1;
    }
}

// all weight transposes (fp32 [K,N] -> fp16 [N,K]) in one launch; z = type*3 + layer
__global__ void transpose_all_kernel(
    const float* __restrict__ w0,  const float* __restrict__ w1,
    const float* __restrict__ w2,  const float* __restrict__ dw0,
    const float* __restrict__ dw1,
    __half* __restrict__ w0T,  __half* __restrict__ w1T,
    __half* __restrict__ w2T,  __half* __restrict__ dw0T,
    __half* __restrict__ dw1T)
{
    const int z = blockIdx.z;
    const int type = z / 3, layer = z % 3;
    const float* in; __half* out; int K, N;
    switch (type) {
        case 0: in = w0  + (size_t)layer*MIN_*NF; out = w0T  + (size_t)layer*NF*MIN_; K = MIN_; N = NF;   break;
        case 1: in = w1  + (size_t)layer*NF*NF;   out = w1T  + (size_t)layer*NF*NF;   K = NF;   N = NF;   break;
        case 2: in = w2  + (size_t)layer*NF*NF;   out = w2T  + (size_t)layer*NF*NF;   K = NF;   N = NF;   break;
        case 3: in = dw0 + (size_t)layer*NF*MIN_; out = dw0T + (size_t)layer*MIN_*NF; K = NF;   N = MIN_; break;
        default:in = dw1 + (size_t)layer*MIN_*NF; out = dw1T + (size_t)layer*NF*MIN_; K = MIN_; N = NF;   break;
    }
    const int k0 = blockIdx.x * 32, n0 = blockIdx.y * 32;
    if (k0 >= K || n0 >= N) return;

    __shared__ float t[32][33];
    const int x = threadIdx.x, y = threadIdx.y;
    #pragma unroll
    for (int i = y; i < 32; i += 8)
        t[i][x] = in[(size_t)(k0 + i) * N + n0 + x];
    __syncthreads();
    #pragma unroll
    for (int i = y; i < 32; i += 8)
        out[(size_t)(n0 + i) * K + k0 + x] = __float2half(t[x][i]);
}

// ---------------- host orchestration ----------------
static inline void launch_gemm(bool smallTile,
                               const __half* A, const __half* Bt, void* D,
                               int M, int N, int K, int lda, int ldB,
                               const float* bias, float alpha, float beta, int flags,
                               const float* addA = nullptr, const float* addC = nullptr,
                               const int* idxFlat = nullptr,
                               const __half* A2 = nullptr, const __half* Bt2 = nullptr,
                               void* D2 = nullptr, int splitK = 1)
{
    const int bm = smallTile ? 64 : 128;
    dim3 grid(M / bm, N / 128, splitK > 1 ? splitK : (A2 ? 2 : 1));
    if (smallTile)
        gemm_f16_kernel<2, false><<<grid, 256, GEMM_SMEM_BYTES>>>(
            A, Bt, D, M, N, K, lda, ldB, bias, alpha, beta, flags,
            addA, addC, idxFlat, A2, Bt2, D2, nullptr, splitK);
    else
        gemm_f16_kernel<4, false><<<grid, 256, GEMM_SMEM_BYTES>>>(
            A, Bt, D, M, N, K, lda, ldB, bias, alpha, beta, flags,
            addA, addC, idxFlat, A2, Bt2, D2, nullptr, splitK);
}

static inline void launch_gemm_red(const __half* A, const __half* Bt, float* Pred,
                                   int M, int N, int K, int lda, int ldB,
                                   const float* bias)
{
    dim3 grid(M / 128, N / 128, 1);
    gemm_f16_kernel<4, true><<<grid, 256, GEMM_SMEM_BYTES>>>(
        A, Bt, nullptr, M, N, K, lda, ldB, bias, 1.f, 1.f, 1,
        nullptr, nullptr, nullptr, nullptr, nullptr, nullptr, Pred, 1);
}

extern "C" void kernel_launch(void* const* d_in, const int* in_sizes, int n_in,
                              void* d_out, int out_size)
{
    (void)in_sizes; (void)n_in; (void)out_size;

    const float* node  = (const float*)d_in[0];
    const float* edges = (const float*)d_in[1];
    const int*   nidx  = (const int*)  d_in[2];
    const float* mask  = (const float*)d_in[3];
    const float* w0    = (const float*)d_in[4];
    const float* b0    = (const float*)d_in[5];
    const float* w1    = (const float*)d_in[6];
    const float* b1    = (const float*)d_in[7];
    const float* w2    = (const float*)d_in[8];
    const float* b2    = (const float*)d_in[9];
    const float* ln1w  = (const float*)d_in[10];
    const float* ln1b  = (const float*)d_in[11];
    const float* dw0   = (const float*)d_in[12];
    const float* db0   = (const float*)d_in[13];
    const float* dw1   = (const float*)d_in[14];
    const float* db1   = (const float*)d_in[15];
    const float* ln2w  = (const float*)d_in[16];
    const float* ln2b  = (const float*)d_in[17];

    __half *ET, *H1, *T, *Xt, *NT, *X1t, *Sb;
    __half *w0T, *w1T, *w2T, *dw0T, *dw1T;
    float *Pp, *Ab, *Cb, *AGGP, *DP, *X, *X1;
    cudaGetSymbolAddress((void**)&ET,   g_ET);
    cudaGetSymbolAddress((void**)&H1,   g_H1);
    cudaGetSymbolAddress((void**)&T,    g_T);
    cudaGetSymbolAddress((void**)&Xt,   g_Xt);
    cudaGetSymbolAddress((void**)&NT,   g_NT);
    cudaGetSymbolAddress((void**)&X1t,  g_X1t);
    cudaGetSymbolAddress((void**)&Sb,   g_Sb);
    cudaGetSymbolAddress((void**)&Pp,   g_P);
    cudaGetSymbolAddress((void**)&Ab,   g_A);
    cudaGetSymbolAddress((void**)&Cb,   g_C);
    cudaGetSymbolAddress((void**)&AGGP, g_AGGP);
    cudaGetSymbolAddress((void**)&DP,   g_DP);
    cudaGetSymbolAddress((void**)&X,    g_X);
    cudaGetSymbolAddress((void**)&X1,   g_X1);
    cudaGetSymbolAddress((void**)&w0T,  g_w0T);
    cudaGetSymbolAddress((void**)&w1T,  g_w1T);
    cudaGetSymbolAddress((void**)&w2T,  g_w2T);
    cudaGetSymbolAddress((void**)&dw0T, g_dw0T);
    cudaGetSymbolAddress((void**)&dw1T, g_dw1T);

    cudaFuncSetAttribute((const void*)gemm_f16_kernel<4, false>,
                         cudaFuncAttributeMaxDynamicSharedMemorySize, GEMM_SMEM_BYTES);
    cudaFuncSetAttribute((const void*)gemm_f16_kernel<2, false>,
                         cudaFuncAttributeMaxDynamicSharedMemorySize, GEMM_SMEM_BYTES);
    cudaFuncSetAttribute((const void*)gemm_f16_kernel<4, true>,
                         cudaFuncAttributeMaxDynamicSharedMemorySize, GEMM_SMEM_BYTES);

    // ---- preamble: 2 launches, so launch #3 is the big (c) GEMM for ncu ----
    prep_kernel<<<(int)((N4E + 255) / 256), 256>>>(edges, ET, node, X, Xt, NT);  // 0
    transpose_all_kernel<<<dim3(48, 48, 15), dim3(32, 8)>>>(
        w0, w1, w2, dw0, dw1, w0T, w1T, w2T, dw0T, dw1T);                        // 1

    for (int i = 0; i < LAYERS; i++) {
        const __half* w0L  = w0T  + (size_t)i * NF * MIN_;
        const float*  b0L  = b0   + (size_t)i * NF;
        const __half* w1L  = w1T  + (size_t)i * NF * NF;
        const float*  b1L  = b1   + (size_t)i * NF;
        const __half* w2L  = w2T  + (size_t)i * NF * NF;
        const float*  b2L  = b2   + (size_t)i * NF;
        const __half* dw0L = dw0T + (size_t)i * MIN_ * NF;
        const float*  db0L = db0  + (size_t)i * MIN_;
        const __half* dw1L = dw1T + (size_t)i * NF * MIN_;
        const float*  db1L = db1  + (size_t)i * NF;

        // (a)+(b) merged (small tile): Ab = x@W0a + b0 ; Cb = node@W0d   (launch 2)
        launch_gemm(true, Xt, w0L, Ab, NN, NF, NF, NF, MIN_, b0L, 1.f, 1.f, 0,
                    nullptr, nullptr, nullptr,
                    NT, w0L + 1152, Cb);
        // (c) H1 = fp16(gelu(edges @ W0b + A[m/48] + C[idx]))            (launch 3 <- ncu)
        launch_gemm(false, ET, w0L + 384, H1, NROWS, NF, NF, NF, MIN_,
                    nullptr, 1.f, 0.f, 1 | 4 | 8, Ab, Cb, nidx);
        // (d)+(e) fused (DORED instantiation): gelu(H1 @ W1 + b1) -> P
        launch_gemm_red(H1, w1L, Pp, NROWS, NF, NF, NF, NF, b1L);
        // (e') S = fp16(P0 + P1)
        combine_kernel<<<NN, NF>>>(Pp, Sb);
        // (f) AGG parts = (S @ W2)/30 (+ (48/30) b2 in part 0), split-K=3 (small tile)
        launch_gemm(true, Sb, w2L, AGGP, NN, NF, NF, NF, NF, b2L,
                    1.f / 30.f, 48.f / 30.f, 0,
                    nullptr, nullptr, nullptr, nullptr, nullptr, nullptr, 3);
        // (g) x1 = LN(x + sum AGG parts)
        ln_kernel<<<NN, NF>>>(X, AGGP, AGGP + (size_t)NN * NF, AGGP + (size_t)2 * NN * NF,
                              ln1w + (size_t)i * NF, ln1b + (size_t)i * NF,
                              nullptr, X1, X1t);
        // (h) T = fp16(gelu(x1 @ dense_w0 + db0))
        launch_gemm(false, X1t, dw0L, T, NN, MIN_, NF, NF, NF, db0L, 1.f, 1.f, 1 | 8);
        // (i) D parts = T @ dense_w1 (+ db1 in part 0), split-K=3 (small tile)
        launch_gemm(true, T, dw1L, DP, NN, NF, MIN_, MIN_, MIN_, db1L, 1.f, 1.f, 0,
                    nullptr, nullptr, nullptr, nullptr, nullptr, nullptr, 3);
        // (j) x = mask * LN(x1 + sum D parts)
        float*  xout  = (i == LAYERS - 1) ? (float*)d_out : X;
        __half* xout2 = (i == LAYERS - 1) ? nullptr : Xt;
        ln_kernel<<<NN, NF>>>(X1, DP, DP + (size_t)NN * NF, DP + (size_t)2 * NN * NF,
                              ln2w + (size_t)i * NF, ln2b + (size_t)i * NF,
                              mask, xout, xout2);
    }
}